// round 2
// baseline (speedup 1.0000x reference)
#include <cuda_runtime.h>
#include <cstdint>
#include <cstddef>

#define NB    4
#define NSRC  16384
#define NTGT  4096
#define KNN   32
#define TPB   256
#define NWARP (TPB / 32)
#define TPW   4                    // targets per warp
#define CHUNK 2048                 // float4 elements staged in smem (32KB)
#define FULLM 0xffffffffu

// Output layout (flattened concat of the reference tuple, all float32):
//   patches      [B,NT,K,3]  @ 0
//   patches_idx  [B,NT,K,2]  @ 1572864
//   patches_size [B,NT]      @ 2621440
//   rad          [B,1,1]     @ 2637824
//   patches_dist [B,NT,K]    @ 2637828
#define OFF_PATCH 0
#define OFF_IDX   1572864
#define OFF_SIZE  2621440
#define OFF_RAD   2637824
#define OFF_DIST  2637828

// Scratch: packed (x,y,z,sumsq). __device__ globals (no alloc).
__device__ float4 g_spk[NB * NSRC];
__device__ float4 g_tpk[NB * NTGT];

__global__ void prep_kernel(const float* __restrict__ src,
                            const float* __restrict__ tgt) {
    int i = blockIdx.x * blockDim.x + threadIdx.x;
    if (i < NB * NSRC) {
        float x = src[3 * i + 0], y = src[3 * i + 1], z = src[3 * i + 2];
        float ss = __fadd_rn(__fadd_rn(__fmul_rn(x, x), __fmul_rn(y, y)), __fmul_rn(z, z));
        g_spk[i] = make_float4(x, y, z, ss);
    }
    if (i < NB * NTGT) {
        float x = tgt[3 * i + 0], y = tgt[3 * i + 1], z = tgt[3 * i + 2];
        float tt = __fadd_rn(__fadd_rn(__fmul_rn(x, x), __fmul_rn(y, y)), __fmul_rn(z, z));
        g_tpk[i] = make_float4(x, y, z, tt);
    }
}

// One warp handles TPW=4 consecutive targets. Warp keeps TPW sorted top-32
// lists (rank = lane). Sources scanned in ascending index order so strict-<
// threshold + (<=)-position insertion reproduces top_k tie-break exactly.
__global__ __launch_bounds__(TPB) void knn_kernel(const float* __restrict__ src,
                                                  float* __restrict__ out) {
    __shared__ float4 s_src[CHUNK];

    const int warp = threadIdx.x >> 5;
    const int lane = threadIdx.x & 31;

    // Block covers NWARP*TPW = 32 consecutive targets; never crosses batch.
    const int tg0 = blockIdx.x * (NWARP * TPW) + warp * TPW;  // global target id of t=0
    const int b   = tg0 / NTGT;

    float tx[TPW], ty[TPW], tz[TPW], tt[TPW];
    #pragma unroll
    for (int t = 0; t < TPW; ++t) {
        const float4 T = g_tpk[tg0 + t];
        tx[t] = T.x; ty[t] = T.y; tz[t] = T.z; tt[t] = T.w;
    }

    const float INF = __int_as_float(0x7f800000);
    float lv[TPW]; int li[TPW]; float thr[TPW];
    #pragma unroll
    for (int t = 0; t < TPW; ++t) { lv[t] = INF; li[t] = -1; thr[t] = INF; }

    const float4* sb = g_spk + b * NSRC;

    for (int c = 0; c < NSRC; c += CHUNK) {
        __syncthreads();
        #pragma unroll
        for (int i = threadIdx.x; i < CHUNK; i += TPB) s_src[i] = sb[c + i];
        __syncthreads();

        #pragma unroll 4
        for (int it = 0; it < CHUNK / 32; ++it) {
            const float4 S = s_src[it * 32 + lane];
            float sq[TPW];
            #pragma unroll
            for (int t = 0; t < TPW; ++t) {
                // dot: FMA accumulation chain (matches reference rounding)
                float dot = __fmaf_rn(tz[t], S.z, __fmaf_rn(ty[t], S.y, __fmul_rn(tx[t], S.x)));
                sq[t] = __fadd_rn(__fsub_rn(tt[t], __fmul_rn(2.0f, dot)), S.w);
            }
            const int j = c + it * 32 + lane;
            #pragma unroll
            for (int t = 0; t < TPW; ++t) {
                unsigned ball = __ballot_sync(FULLM, sq[t] < thr[t]);
                if (ball) {
                    do {
                        const int   sl = __ffs(ball) - 1;
                        ball &= ball - 1;
                        const float nv = __shfl_sync(FULLM, sq[t], sl);
                        const int   nj = __shfl_sync(FULLM, j,     sl);
                        const unsigned le = __ballot_sync(FULLM, lv[t] <= nv);
                        const int pos = __popc(le);
                        if (pos < 32) {
                            const float pv = __shfl_up_sync(FULLM, lv[t], 1);
                            const int   pj = __shfl_up_sync(FULLM, li[t], 1);
                            if (lane > pos)       { lv[t] = pv; li[t] = pj; }
                            else if (lane == pos) { lv[t] = nv; li[t] = nj; }
                        }
                    } while (ball);
                    thr[t] = __shfl_sync(FULLM, lv[t], 31);
                }
            }
        }
    }

    // ---- outputs ----
    const float rad  = 0.2f;
    const float rad2 = __fmul_rn(rad, rad);

    #pragma unroll
    for (int t = 0; t < TPW; ++t) {
        const int  tg   = tg0 + t;
        const bool mask = (rad2 >= lv[t]);

        float gx = 0.0f, gy = 0.0f, gz = 0.0f;
        if (mask) {
            const float* sp = src + (size_t)(b * NSRC + li[t]) * 3;
            gx = __fdiv_rn(sp[0], rad);
            gy = __fdiv_rn(sp[1], rad);
            gz = __fdiv_rn(sp[2], rad);
        }
        const float tdx = __fdiv_rn(tx[t], rad);
        const float tdy = __fdiv_rn(ty[t], rad);
        const float tdz = __fdiv_rn(tz[t], rad);

        const size_t e = (size_t)tg * KNN + lane;

        float* patches = out + OFF_PATCH;
        patches[3 * e + 0] = __fsub_rn(gx, tdx);
        patches[3 * e + 1] = __fsub_rn(gy, tdy);
        patches[3 * e + 2] = __fsub_rn(gz, tdz);

        float* idxf = out + OFF_IDX;
        idxf[2 * e + 0] = (float)b;
        idxf[2 * e + 1] = (float)(mask ? li[t] : -1);

        float* pdist = out + OFF_DIST;
        pdist[e] = __fdiv_rn(__fsqrt_rn(fmaxf(lv[t], 1e-9f)), rad);

        const unsigned mball = __ballot_sync(FULLM, mask);
        if (lane == 0) {
            float* psize = out + OFF_SIZE;
            psize[tg] = (float)__popc(mball);
        }
    }

    if (blockIdx.x == 0 && threadIdx.x < NB) {
        float* prad = out + OFF_RAD;
        prad[threadIdx.x] = rad;
    }
}

extern "C" void kernel_launch(void* const* d_in, const int* in_sizes, int n_in,
                              void* d_out, int out_size) {
    const float* src = (const float*)d_in[0];
    const float* tgt = (const float*)d_in[1];
    if (n_in >= 2 && in_sizes[0] == NB * NTGT * 3 && in_sizes[1] == NB * NSRC * 3) {
        src = (const float*)d_in[1];
        tgt = (const float*)d_in[0];
    }
    float* out = (float*)d_out;

    prep_kernel<<<(NB * NSRC + 255) / 256, 256>>>(src, tgt);
    knn_kernel<<<(NB * NTGT) / (NWARP * TPW), TPB>>>(src, out);
}

// round 3
// speedup vs baseline: 1.1055x; 1.1055x over previous
#include <cuda_runtime.h>
#include <cstdint>
#include <cstddef>

#define NB    4
#define NSRC  16384
#define NTGT  4096
#define KNN   32
#define TPB   256
#define NWARP (TPB / 32)
#define TPW   2                    // targets per warp
#define CHUNK 2048                 // float4 elements staged in smem (32KB)
#define FULLM 0xffffffffu

// Output layout (flattened concat of the reference tuple, all float32):
#define OFF_PATCH 0
#define OFF_IDX   1572864
#define OFF_SIZE  2621440
#define OFF_RAD   2637824
#define OFF_DIST  2637828

// Scratch: packed (x,y,z,sumsq). __device__ globals (no alloc).
__device__ float4 g_spk[NB * NSRC];
__device__ float4 g_tpk[NB * NTGT];

__global__ void prep_kernel(const float* __restrict__ src,
                            const float* __restrict__ tgt) {
    int i = blockIdx.x * blockDim.x + threadIdx.x;
    if (i < NB * NSRC) {
        float x = src[3 * i + 0], y = src[3 * i + 1], z = src[3 * i + 2];
        float ss = __fadd_rn(__fadd_rn(__fmul_rn(x, x), __fmul_rn(y, y)), __fmul_rn(z, z));
        g_spk[i] = make_float4(x, y, z, ss);
    }
    if (i < NB * NTGT) {
        float x = tgt[3 * i + 0], y = tgt[3 * i + 1], z = tgt[3 * i + 2];
        float tt = __fadd_rn(__fadd_rn(__fmul_rn(x, x), __fmul_rn(y, y)), __fmul_rn(z, z));
        g_tpk[i] = make_float4(x, y, z, tt);
    }
}

// One warp handles TPW=2 consecutive targets; warp keeps TPW sorted top-32
// lists (rank = lane). Sources scanned in ascending index order so strict-<
// threshold + (<=)-position insertion reproduces top_k tie-break exactly.
__global__ __launch_bounds__(TPB) void knn_kernel(const float* __restrict__ src,
                                                  float* __restrict__ out) {
    __shared__ float4 s_src[CHUNK];

    const int warp = threadIdx.x >> 5;
    const int lane = threadIdx.x & 31;

    // Block covers NWARP*TPW = 16 consecutive targets; never crosses batch.
    const int tg0 = blockIdx.x * (NWARP * TPW) + warp * TPW;
    const int b   = tg0 / NTGT;

    float tx[TPW], ty[TPW], tz[TPW], tt[TPW];
    #pragma unroll
    for (int t = 0; t < TPW; ++t) {
        const float4 T = g_tpk[tg0 + t];
        tx[t] = T.x; ty[t] = T.y; tz[t] = T.z; tt[t] = T.w;
    }

    const float INF = __int_as_float(0x7f800000);
    float lv[TPW]; int li[TPW]; float thr[TPW];
    #pragma unroll
    for (int t = 0; t < TPW; ++t) { lv[t] = INF; li[t] = -1; thr[t] = INF; }

    const float4* sb = g_spk + b * NSRC;

    for (int c = 0; c < NSRC; c += CHUNK) {
        __syncthreads();
        #pragma unroll
        for (int i = threadIdx.x; i < CHUNK; i += TPB) s_src[i] = sb[c + i];
        __syncthreads();

        #pragma unroll 4
        for (int it = 0; it < CHUNK / 32; ++it) {
            const float4 S = s_src[it * 32 + lane];
            float sq[TPW];
            #pragma unroll
            for (int t = 0; t < TPW; ++t) {
                float dot = __fmaf_rn(tz[t], S.z, __fmaf_rn(ty[t], S.y, __fmul_rn(tx[t], S.x)));
                sq[t] = __fadd_rn(__fsub_rn(tt[t], __fmul_rn(2.0f, dot)), S.w);
            }
            // fast path: one combined ballot; usually zero in the late phase
            bool any = false;
            #pragma unroll
            for (int t = 0; t < TPW; ++t) any |= (sq[t] < thr[t]);
            if (__ballot_sync(FULLM, any)) {
                const int j = c + it * 32 + lane;
                #pragma unroll
                for (int t = 0; t < TPW; ++t) {
                    unsigned ball = __ballot_sync(FULLM, sq[t] < thr[t]);
                    while (ball) {
                        const int   sl = __ffs(ball) - 1;
                        ball &= ball - 1;
                        const float nv = __shfl_sync(FULLM, sq[t], sl);
                        const int   nj = __shfl_sync(FULLM, j,     sl);
                        const unsigned le = __ballot_sync(FULLM, lv[t] <= nv);
                        const int pos = __popc(le);
                        if (pos < 32) {
                            const float pv = __shfl_up_sync(FULLM, lv[t], 1);
                            const int   pj = __shfl_up_sync(FULLM, li[t], 1);
                            if (lane > pos)       { lv[t] = pv; li[t] = pj; }
                            else if (lane == pos) { lv[t] = nv; li[t] = nj; }
                        }
                    }
                    thr[t] = __shfl_sync(FULLM, lv[t], 31);
                }
            }
        }
    }

    // ---- outputs ----
    const float rad  = 0.2f;
    const float rad2 = __fmul_rn(rad, rad);

    #pragma unroll
    for (int t = 0; t < TPW; ++t) {
        const int  tg   = tg0 + t;
        const bool mask = (rad2 >= lv[t]);

        float gx = 0.0f, gy = 0.0f, gz = 0.0f;
        if (mask) {
            const float* sp = src + (size_t)(b * NSRC + li[t]) * 3;
            gx = __fdiv_rn(sp[0], rad);
            gy = __fdiv_rn(sp[1], rad);
            gz = __fdiv_rn(sp[2], rad);
        }
        const float tdx = __fdiv_rn(tx[t], rad);
        const float tdy = __fdiv_rn(ty[t], rad);
        const float tdz = __fdiv_rn(tz[t], rad);

        const size_t e = (size_t)tg * KNN + lane;

        float* patches = out + OFF_PATCH;
        patches[3 * e + 0] = __fsub_rn(gx, tdx);
        patches[3 * e + 1] = __fsub_rn(gy, tdy);
        patches[3 * e + 2] = __fsub_rn(gz, tdz);

        float* idxf = out + OFF_IDX;
        idxf[2 * e + 0] = (float)b;
        idxf[2 * e + 1] = (float)(mask ? li[t] : -1);

        float* pdist = out + OFF_DIST;
        pdist[e] = __fdiv_rn(__fsqrt_rn(fmaxf(lv[t], 1e-9f)), rad);

        const unsigned mball = __ballot_sync(FULLM, mask);
        if (lane == 0) {
            float* psize = out + OFF_SIZE;
            psize[tg] = (float)__popc(mball);
        }
    }

    if (blockIdx.x == 0 && threadIdx.x < NB) {
        float* prad = out + OFF_RAD;
        prad[threadIdx.x] = rad;
    }
}

extern "C" void kernel_launch(void* const* d_in, const int* in_sizes, int n_in,
                              void* d_out, int out_size) {
    const float* src = (const float*)d_in[0];
    const float* tgt = (const float*)d_in[1];
    if (n_in >= 2 && in_sizes[0] == NB * NTGT * 3 && in_sizes[1] == NB * NSRC * 3) {
        src = (const float*)d_in[1];
        tgt = (const float*)d_in[0];
    }
    float* out = (float*)d_out;

    prep_kernel<<<(NB * NSRC + 255) / 256, 256>>>(src, tgt);
    knn_kernel<<<(NB * NTGT) / (NWARP * TPW), TPB>>>(src, out);
}